// round 3
// baseline (speedup 1.0000x reference)
#include <cuda_runtime.h>

// CrossAttention collapses: softmax over a singleton axis == 1, so
//   out = chem @ (Wout @ Wv)^T + (Wout @ bv + bout).
// Setup kernel folds weights; main kernel is a memory-bound streaming
// 16x16 matvec using packed f32x2 FMA (2 rows per thread in the 64-bit halves).

#define DIMN   16
#define BLOCK  256
#define RPT    2
#define TILE   (BLOCK * RPT)   // 512 rows per block
#define PADW   20              // padded floats per row in smem (bank-conflict-free, 16B aligned)

__device__ float2 g_Mdup[DIMN * DIMN];  // (m, m) duplicated for packed FMA
__device__ float2 g_cdup[DIMN];         // (c, c)

__global__ void setup_kernel(const float* __restrict__ w_in,
                             const float* __restrict__ b_in,
                             const float* __restrict__ w_out,
                             const float* __restrict__ b_out) {
    int t = threadIdx.x;          // 256 threads: t = j*16 + i
    int j = t >> 4, i = t & 15;
    float m = 0.0f;
#pragma unroll
    for (int k = 0; k < DIMN; k++)
        m += w_out[j * DIMN + k] * w_in[(2 * DIMN + k) * DIMN + i];  // Wv rows = 32..47
    g_Mdup[t] = make_float2(m, m);
    if (i == 0) {
        float c = b_out[j];
#pragma unroll
        for (int k = 0; k < DIMN; k++)
            c += w_out[j * DIMN + k] * b_in[2 * DIMN + k];
        g_cdup[j] = make_float2(c, c);
    }
}

__device__ __forceinline__ unsigned long long pack2f(float lo, float hi) {
    unsigned long long r;
    asm("mov.b64 %0, {%1, %2};" : "=l"(r) : "f"(lo), "f"(hi));
    return r;
}
__device__ __forceinline__ void unpack2f(unsigned long long v, float& lo, float& hi) {
    asm("mov.b64 {%0, %1}, %2;" : "=f"(lo), "=f"(hi) : "l"(v));
}
__device__ __forceinline__ void ffma2(unsigned long long& d,
                                      unsigned long long a,
                                      unsigned long long b) {
    asm("fma.rn.f32x2 %0, %1, %2, %3;" : "=l"(d) : "l"(a), "l"(b), "l"(d));
}

__global__ __launch_bounds__(BLOCK)
void xattn_kernel(const float* __restrict__ chem,
                  float* __restrict__ outp,
                  int nrows) {
    __shared__ float  sbuf[TILE * PADW];     // 40 KB staging tile (in, then out)
    __shared__ float2 sM[DIMN * DIMN];       // duplicated M
    __shared__ float2 sC[DIMN];              // duplicated bias

    int t = threadIdx.x;
    sM[t] = g_Mdup[t];
    if (t < DIMN) sC[t] = g_cdup[t];

    long long rowbase = (long long)blockIdx.x * TILE;
    long long q4base  = rowbase * 4;                 // float4 index of tile start
    long long total4  = (long long)nrows * 4;
    const float4* gin  = (const float4*)chem;
    float4*       gout = (float4*)outp;

    // ---- stage in: perfectly coalesced G -> S ----
#pragma unroll
    for (int k = 0; k < (TILE * 4) / BLOCK; k++) {   // 8 iters
        long long g = q4base + t + k * BLOCK;
        int lg = t + k * BLOCK;
        float4 v = (g < total4) ? gin[g] : make_float4(0.f, 0.f, 0.f, 0.f);
        int row = lg >> 2, q = lg & 3;
        *(float4*)&sbuf[row * PADW + q * 4] = v;
    }
    __syncthreads();

    // ---- read my two rows (t and t+256), pack immediately into f32x2 operands ----
    int r0 = t, r1 = t + BLOCK;
    unsigned long long ax[DIMN];
#pragma unroll
    for (int q = 0; q < 4; q++) {
        float4 v0 = *(const float4*)&sbuf[r0 * PADW + q * 4];
        float4 v1 = *(const float4*)&sbuf[r1 * PADW + q * 4];
        ax[q * 4 + 0] = pack2f(v0.x, v1.x);
        ax[q * 4 + 1] = pack2f(v0.y, v1.y);
        ax[q * 4 + 2] = pack2f(v0.z, v1.z);
        ax[q * 4 + 3] = pack2f(v0.w, v1.w);
    }
    __syncthreads();   // everyone done reading sbuf before it is overwritten

    // ---- compute: 16 outputs x 16 inputs, two rows per FFMA2 ----
    unsigned long long acc[DIMN];
#pragma unroll
    for (int j = 0; j < DIMN; j++)
        acc[j] = *(const unsigned long long*)&sC[j];
#pragma unroll
    for (int j = 0; j < DIMN; j++) {
#pragma unroll
        for (int i = 0; i < DIMN; i++) {
            unsigned long long m = *(const unsigned long long*)&sM[j * DIMN + i];
            ffma2(acc[j], ax[i], m);
        }
    }

    // ---- unpack and write results back to smem (conflict-free STS.128) ----
    float o0[DIMN], o1[DIMN];
#pragma unroll
    for (int j = 0; j < DIMN; j++)
        unpack2f(acc[j], o0[j], o1[j]);
#pragma unroll
    for (int q = 0; q < 4; q++) {
        *(float4*)&sbuf[r0 * PADW + q * 4] =
            make_float4(o0[q * 4 + 0], o0[q * 4 + 1], o0[q * 4 + 2], o0[q * 4 + 3]);
        *(float4*)&sbuf[r1 * PADW + q * 4] =
            make_float4(o1[q * 4 + 0], o1[q * 4 + 1], o1[q * 4 + 2], o1[q * 4 + 3]);
    }
    __syncthreads();

    // ---- stage out: perfectly coalesced S -> G ----
#pragma unroll
    for (int k = 0; k < (TILE * 4) / BLOCK; k++) {
        long long g = q4base + t + k * BLOCK;
        int lg = t + k * BLOCK;
        if (g < total4) {
            int row = lg >> 2, q = lg & 3;
            gout[g] = *(const float4*)&sbuf[row * PADW + q * 4];
        }
    }
}

extern "C" void kernel_launch(void* const* d_in, const int* in_sizes, int n_in,
                              void* d_out, int out_size) {
    // inputs: 0 fp_16 (unused), 1 chem_16, 2 in_proj_weight, 3 in_proj_bias,
    //         4 out_proj_weight, 5 out_proj_bias
    const float* chem  = (const float*)d_in[1];
    const float* w_in  = (const float*)d_in[2];
    const float* b_in  = (const float*)d_in[3];
    const float* w_out = (const float*)d_in[4];
    const float* b_out = (const float*)d_in[5];
    float* outp = (float*)d_out;

    int nrows = in_sizes[1] / DIMN;
    setup_kernel<<<1, 256>>>(w_in, b_in, w_out, b_out);
    int nblocks = (nrows + TILE - 1) / TILE;
    xattn_kernel<<<nblocks, BLOCK>>>(chem, outp, nrows);
}

// round 4
// speedup vs baseline: 1.1754x; 1.1754x over previous
#include <cuda_runtime.h>

// out = chem @ (Wout @ Wv)^T + (Wout @ bv + bout)   (softmax over singleton == 1)
// Streaming 16x16 matvec, f32x2-packed (2 rows per thread), XOR-swizzled smem
// transpose staging, paired-M LDS.128 (one smem load per two FFMA2).

#define DIMN   16
#define BLOCK  256
#define TILE   512              // rows per block

__device__ float2 g_Mdup[DIMN * DIMN];  // (m, m) duplicated for packed FMA
__device__ float2 g_cdup[DIMN];         // (c, c)

__global__ void setup_kernel(const float* __restrict__ w_in,
                             const float* __restrict__ b_in,
                             const float* __restrict__ w_out,
                             const float* __restrict__ b_out) {
    int t = threadIdx.x;          // 256 threads: t = j*16 + i
    int j = t >> 4, i = t & 15;
    float m = 0.0f;
#pragma unroll
    for (int k = 0; k < DIMN; k++)
        m += w_out[j * DIMN + k] * w_in[(2 * DIMN + k) * DIMN + i];  // Wv rows 32..47
    g_Mdup[t] = make_float2(m, m);
    if (i == 0) {
        float c = b_out[j];
#pragma unroll
        for (int k = 0; k < DIMN; k++)
            c += w_out[j * DIMN + k] * b_in[2 * DIMN + k];
        g_cdup[j] = make_float2(c, c);
    }
}

__device__ __forceinline__ unsigned long long pack2f(float lo, float hi) {
    unsigned long long r;
    asm("mov.b64 %0, {%1, %2};" : "=l"(r) : "f"(lo), "f"(hi));
    return r;
}
__device__ __forceinline__ void unpack2f(unsigned long long v, float& lo, float& hi) {
    asm("mov.b64 {%0, %1}, %2;" : "=f"(lo), "=f"(hi) : "l"(v));
}
__device__ __forceinline__ void ffma2(unsigned long long& d,
                                      unsigned long long a,
                                      unsigned long long b) {
    asm("fma.rn.f32x2 %0, %1, %2, %3;" : "=l"(d) : "l"(a), "l"(b), "l"(d));
}

// XOR swizzle in float4-slot space: conflict-free for both coalesced
// (consecutive p) and per-row (stride-4 p) 128-bit phases.
__device__ __forceinline__ int sw(int p) { return p ^ ((p >> 3) & 3); }

__global__ __launch_bounds__(BLOCK, 4)
void xattn_kernel(const float* __restrict__ chem,
                  float* __restrict__ outp,
                  int nrows) {
    __shared__ float4 sbuf[TILE * 4];                 // 32 KB swizzled tile
    __shared__ __align__(16) float2 sM[DIMN * DIMN];  // dup pairs, [j*16 + i]
    __shared__ float2 sC[DIMN];

    int t = threadIdx.x;
    sM[t] = g_Mdup[t];
    if (t < DIMN) sC[t] = g_cdup[t];

    long long q4base = (long long)blockIdx.x * (TILE * 4);
    long long total4 = (long long)nrows * 4;
    const float4* gin  = (const float4*)chem;
    float4*       gout = (float4*)outp;

    // ---- stage in: coalesced G -> S (swizzled) ----
#pragma unroll
    for (int k = 0; k < 8; k++) {
        int p = t + k * BLOCK;
        long long g = q4base + p;
        float4 v = (g < total4) ? __ldcs(&gin[g]) : make_float4(0.f, 0.f, 0.f, 0.f);
        sbuf[sw(p)] = v;
    }
    __syncthreads();

    // ---- gather my two rows (t, t+256), pack into f32x2 operands ----
    int r0 = t, r1 = t + BLOCK;
    unsigned long long ax[DIMN];
#pragma unroll
    for (int q = 0; q < 4; q++) {
        float4 v0 = sbuf[r0 * 4 + (q ^ ((r0 >> 1) & 3))];
        float4 v1 = sbuf[r1 * 4 + (q ^ ((r1 >> 1) & 3))];
        ax[q * 4 + 0] = pack2f(v0.x, v1.x);
        ax[q * 4 + 1] = pack2f(v0.y, v1.y);
        ax[q * 4 + 2] = pack2f(v0.z, v1.z);
        ax[q * 4 + 3] = pack2f(v0.w, v1.w);
    }

    // ---- compute 4 outputs at a time; write back to own slots immediately.
    //      (No sync needed: each slot is touched only by its owner thread.)
#pragma unroll
    for (int jq = 0; jq < 4; jq++) {
        unsigned long long acc[4];
#pragma unroll
        for (int jj = 0; jj < 4; jj++)
            acc[jj] = *(const unsigned long long*)&sC[jq * 4 + jj];
#pragma unroll
        for (int ih = 0; ih < 8; ih++) {
#pragma unroll
            for (int jj = 0; jj < 4; jj++) {
                ulonglong2 m = *(const ulonglong2*)&sM[(jq * 4 + jj) * DIMN + ih * 2];
                ffma2(acc[jj], ax[2 * ih + 0], m.x);
                ffma2(acc[jj], ax[2 * ih + 1], m.y);
            }
        }
        float lo0, hi0, lo1, hi1, lo2, hi2, lo3, hi3;
        unpack2f(acc[0], lo0, hi0);
        unpack2f(acc[1], lo1, hi1);
        unpack2f(acc[2], lo2, hi2);
        unpack2f(acc[3], lo3, hi3);
        sbuf[r0 * 4 + (jq ^ ((r0 >> 1) & 3))] = make_float4(lo0, lo1, lo2, lo3);
        sbuf[r1 * 4 + (jq ^ ((r1 >> 1) & 3))] = make_float4(hi0, hi1, hi2, hi3);
    }
    __syncthreads();

    // ---- stage out: coalesced S -> G ----
#pragma unroll
    for (int k = 0; k < 8; k++) {
        int p = t + k * BLOCK;
        long long g = q4base + p;
        if (g < total4) __stcs(&gout[g], sbuf[sw(p)]);
    }
}

extern "C" void kernel_launch(void* const* d_in, const int* in_sizes, int n_in,
                              void* d_out, int out_size) {
    // inputs: 0 fp_16 (unused), 1 chem_16, 2 in_proj_weight, 3 in_proj_bias,
    //         4 out_proj_weight, 5 out_proj_bias
    const float* chem  = (const float*)d_in[1];
    const float* w_in  = (const float*)d_in[2];
    const float* b_in  = (const float*)d_in[3];
    const float* w_out = (const float*)d_in[4];
    const float* b_out = (const float*)d_in[5];
    float* outp = (float*)d_out;

    int nrows = in_sizes[1] / DIMN;
    setup_kernel<<<1, 256>>>(w_in, b_in, w_out, b_out);
    int nblocks = (nrows + TILE - 1) / TILE;
    xattn_kernel<<<nblocks, BLOCK>>>(chem, outp, nrows);
}

// round 5
// speedup vs baseline: 1.3362x; 1.1368x over previous
#include <cuda_runtime.h>

// out = chem @ (Wout @ Wv)^T + (Wout @ bv + bout)   (softmax over singleton == 1)
//
// Output-quarter scheme: thread owning float4 p (quarter q=p&3 of row p>>2)
// computes exactly that output float4. Coalesced LDG/STG, no smem staging.
// Row gathered from the 3 sibling lanes via shfl (4x4 float4 transpose per
// lane-quad). M rows for the fixed quarter live in 64 registers as paired
// f32x2 operands -> zero per-task M loads.

#define DIMN 16
#define TPT  8            // float4 tasks per thread

typedef unsigned long long ull;

__device__ float2 g_Bi[128];   // [i*8 + q*2 + a] = (M[4q+2a][i], M[4q+2a+1][i])
__device__ float2 g_Cp[8];     // [q*2 + a]       = (c[4q+2a],   c[4q+2a+1])

__global__ void setup_kernel(const float* __restrict__ w_in,
                             const float* __restrict__ b_in,
                             const float* __restrict__ w_out,
                             const float* __restrict__ b_out) {
    int t = threadIdx.x;
    if (t < 128) {                       // t == i*8 + q*2 + a
        int i = t >> 3, q = (t >> 1) & 3, a = t & 1;
        int j0 = 4 * q + 2 * a, j1 = j0 + 1;
        float m0 = 0.f, m1 = 0.f;
#pragma unroll
        for (int k = 0; k < DIMN; k++) {
            float wv = w_in[(2 * DIMN + k) * DIMN + i];   // Wv rows 32..47, col i
            m0 += w_out[j0 * DIMN + k] * wv;
            m1 += w_out[j1 * DIMN + k] * wv;
        }
        g_Bi[t] = make_float2(m0, m1);
    }
    if (t < 8) {                         // t == q*2 + a
        int a = t & 1;
        int j0 = 4 * (t >> 1) + 2 * a;
        float c0 = b_out[j0], c1 = b_out[j0 + 1];
#pragma unroll
        for (int k = 0; k < DIMN; k++) {
            float bv = b_in[2 * DIMN + k];
            c0 += w_out[j0 * DIMN + k] * bv;
            c1 += w_out[(j0 + 1) * DIMN + k] * bv;
        }
        g_Cp[t] = make_float2(c0, c1);
    }
}

__device__ __forceinline__ ull dup2f(float v) {
    ull r;
    asm("mov.b64 %0, {%1, %1};" : "=l"(r) : "f"(v));
    return r;
}
__device__ __forceinline__ void unpack2f(ull v, float& lo, float& hi) {
    asm("mov.b64 {%0, %1}, %2;" : "=f"(lo), "=f"(hi) : "l"(v));
}
__device__ __forceinline__ void ffma2(ull& d, ull a, ull b) {
    asm("fma.rn.f32x2 %0, %1, %2, %3;" : "=l"(d) : "l"(a), "l"(b), "l"(d));
}

__global__ __launch_bounds__(256, 2)
void xattn_kernel(const float4* __restrict__ gin,
                  float4* __restrict__ gout,
                  long long total4, long long stride) {
    __shared__ __align__(16) float2 sB[128];
    __shared__ float2 sC[8];
    int t = threadIdx.x;
    if (t < 128) sB[t] = g_Bi[t];
    if (t < 8)   sC[t] = g_Cp[t];
    __syncthreads();

    const int lane = t & 31;
    const int q    = t & 3;           // my output quarter (constant per thread)
    const int qbase = lane & ~3;      // first lane of my quad

    // M rows for quarter q -> 64 registers of paired f32x2 operands.
    ull B0[DIMN], B1[DIMN];
#pragma unroll
    for (int i = 0; i < DIMN; i++) {
        ulonglong2 bb = *(const ulonglong2*)&sB[i * 8 + q * 2];
        B0[i] = bb.x;                 // (M[4q+0][i], M[4q+1][i])
        B1[i] = bb.y;                 // (M[4q+2][i], M[4q+3][i])
    }
    ull c0 = *(const ull*)&sC[q * 2 + 0];
    ull c1 = *(const ull*)&sC[q * 2 + 1];

    long long gtid = (long long)blockIdx.x * 256 + t;

    // Front-batch all loads: MLP = 8 per warp-lane.
    float4 v[TPT];
#pragma unroll
    for (int k = 0; k < TPT; k++) {
        long long p = gtid + (long long)k * stride;
        v[k] = (p < total4) ? __ldcs(&gin[p]) : make_float4(0.f, 0.f, 0.f, 0.f);
    }

#pragma unroll
    for (int k = 0; k < TPT; k++) {
        // Gather the full 16-float row from my lane-quad (4x4 float4 transpose).
        float x[DIMN];
#pragma unroll
        for (int m = 0; m < 4; m++) {
            x[4 * m + 0] = __shfl_sync(0xffffffffu, v[k].x, qbase + m);
            x[4 * m + 1] = __shfl_sync(0xffffffffu, v[k].y, qbase + m);
            x[4 * m + 2] = __shfl_sync(0xffffffffu, v[k].z, qbase + m);
            x[4 * m + 3] = __shfl_sync(0xffffffffu, v[k].w, qbase + m);
        }
        ull a0 = c0, a1 = c1;
#pragma unroll
        for (int i = 0; i < DIMN; i++) {
            ull xd = dup2f(x[i]);
            ffma2(a0, B0[i], xd);
            ffma2(a1, B1[i], xd);
        }
        long long p = gtid + (long long)k * stride;
        if (p < total4) {
            float o0, o1, o2, o3;
            unpack2f(a0, o0, o1);
            unpack2f(a1, o2, o3);
            __stcs(&gout[p], make_float4(o0, o1, o2, o3));
        }
    }
}

extern "C" void kernel_launch(void* const* d_in, const int* in_sizes, int n_in,
                              void* d_out, int out_size) {
    // inputs: 0 fp_16 (unused), 1 chem_16, 2 in_proj_weight, 3 in_proj_bias,
    //         4 out_proj_weight, 5 out_proj_bias
    const float* chem  = (const float*)d_in[1];
    const float* w_in  = (const float*)d_in[2];
    const float* b_in  = (const float*)d_in[3];
    const float* w_out = (const float*)d_in[4];
    const float* b_out = (const float*)d_in[5];

    int nrows = in_sizes[1] / DIMN;
    long long total4 = (long long)nrows * 4;

    setup_kernel<<<1, 256>>>(w_in, b_in, w_out, b_out);

    long long blocks = (total4 + 256LL * TPT - 1) / (256LL * TPT);
    long long stride = blocks * 256;   // multiple of 4 -> quarter fixed per thread
    xattn_kernel<<<(int)blocks, 256>>>((const float4*)chem, (float4*)d_out,
                                       total4, stride);
}

// round 6
// speedup vs baseline: 1.3843x; 1.0360x over previous
#include <cuda_runtime.h>

// out = chem @ (Wout @ Wv)^T + (Wout @ bv + bout)   (softmax over singleton == 1)
//
// Partial-sum scheme: each lane computes partials for ALL 16 outputs from its
// own loaded float4 (input quarter q = lane&3), using M columns 4q..4q+3 held
// in 64 registers as paired f32x2. A 2-round xor-butterfly reduce-scatter
// across the lane-quad then leaves each lane with its OUTPUT quarter, which it
// stores to the same coalesced address it loaded. No smem in the hot loop,
// FMA chains are depth-4, shfl sits after independent FMA work.

#define DIMN 16
#define TPT  8            // float4 tasks per thread

typedef unsigned long long ull;

__device__ float2 g_B[128];   // [i*8 + p] = (M[2p][i], M[2p+1][i])
__device__ float2 g_c[8];     // [p]       = (c[2p],    c[2p+1])

__global__ void setup_kernel(const float* __restrict__ w_in,
                             const float* __restrict__ b_in,
                             const float* __restrict__ w_out,
                             const float* __restrict__ b_out) {
    int t = threadIdx.x;
    if (t < 128) {                       // t == i*8 + p
        int i = t >> 3, p = t & 7;
        int j0 = 2 * p, j1 = j0 + 1;
        float m0 = 0.f, m1 = 0.f;
#pragma unroll
        for (int k = 0; k < DIMN; k++) {
            float wv = w_in[(2 * DIMN + k) * DIMN + i];   // Wv rows 32..47, col i
            m0 += w_out[j0 * DIMN + k] * wv;
            m1 += w_out[j1 * DIMN + k] * wv;
        }
        g_B[t] = make_float2(m0, m1);
    }
    if (t < 8) {                         // t == p
        int j0 = 2 * t;
        float c0 = b_out[j0], c1 = b_out[j0 + 1];
#pragma unroll
        for (int k = 0; k < DIMN; k++) {
            float bv = b_in[2 * DIMN + k];
            c0 += w_out[j0 * DIMN + k] * bv;
            c1 += w_out[(j0 + 1) * DIMN + k] * bv;
        }
        g_c[t] = make_float2(c0, c1);
    }
}

__device__ __forceinline__ ull dup2f(float v) {
    ull r;
    asm("mov.b64 %0, {%1, %1};" : "=l"(r) : "f"(v));
    return r;
}
__device__ __forceinline__ void unpack2f(ull v, float& lo, float& hi) {
    asm("mov.b64 {%0, %1}, %2;" : "=f"(lo), "=f"(hi) : "l"(v));
}
__device__ __forceinline__ void ffma2(ull& d, ull a, ull b) {
    asm("fma.rn.f32x2 %0, %1, %2, %3;" : "=l"(d) : "l"(a), "l"(b), "l"(d));
}
__device__ __forceinline__ ull mul2(ull a, ull b) {
    ull r;
    asm("mul.rn.f32x2 %0, %1, %2;" : "=l"(r) : "l"(a), "l"(b));
    return r;
}
__device__ __forceinline__ ull add2(ull a, ull b) {
    ull r;
    asm("add.rn.f32x2 %0, %1, %2;" : "=l"(r) : "l"(a), "l"(b));
    return r;
}

__global__ __launch_bounds__(256, 2)
void xattn_kernel(const float4* __restrict__ gin,
                  float4* __restrict__ gout,
                  long long total4, long long stride) {
    __shared__ __align__(16) float2 sB[128];
    __shared__ float2 sC[8];
    int t = threadIdx.x;
    if (t < 128) sB[t] = g_B[t];
    if (t < 8)   sC[t] = g_c[t];
    __syncthreads();

    const int q = t & 3;                 // my input AND output quarter

    // M columns for my input quarter, register-resident, lane-permuted so the
    // butterfly below uses only compile-time shfl/keep indices.
    // Mreg[il][2u+v] = (M[4*(q^u)+2v][4q+il], M[4*(q^u)+2v+1][4q+il])
    ull Mreg[4][8];
#pragma unroll
    for (int il = 0; il < 4; il++) {
        int i = 4 * q + il;
#pragma unroll
        for (int u = 0; u < 4; u++) {
#pragma unroll
            for (int v = 0; v < 2; v++)
                Mreg[il][2 * u + v] = *(const ull*)&sB[i * 8 + 2 * (q ^ u) + v];
        }
    }
    ull cA = *(const ull*)&sC[2 * q + 0];
    ull cB = *(const ull*)&sC[2 * q + 1];

    long long gtid = (long long)blockIdx.x * 256 + t;

    // Front-batch all loads: MLP = 8.
    float4 v[TPT];
#pragma unroll
    for (int k = 0; k < TPT; k++) {
        long long p = gtid + (long long)k * stride;
        v[k] = (p < total4) ? __ldcs(&gin[p]) : make_float4(0.f, 0.f, 0.f, 0.f);
    }

#pragma unroll
    for (int k = 0; k < TPT; k++) {
        // Partials for all 16 outputs from my 4 values (depth-4 chains).
        ull P[8];
        ull xd = dup2f(v[k].x);
#pragma unroll
        for (int m = 0; m < 8; m++) P[m] = mul2(Mreg[0][m], xd);
        xd = dup2f(v[k].y);
#pragma unroll
        for (int m = 0; m < 8; m++) ffma2(P[m], Mreg[1][m], xd);
        xd = dup2f(v[k].z);
#pragma unroll
        for (int m = 0; m < 8; m++) ffma2(P[m], Mreg[2][m], xd);
        xd = dup2f(v[k].w);
#pragma unroll
        for (int m = 0; m < 8; m++) ffma2(P[m], Mreg[3][m], xd);

        // Butterfly reduce-scatter across the lane-quad.
        // Round 1 (xor 2): keep quarters {q, q^1} (P[0..3]), fold in partner's.
        ull A0 = add2(P[0], __shfl_xor_sync(0xffffffffu, P[4], 2));
        ull A1 = add2(P[1], __shfl_xor_sync(0xffffffffu, P[5], 2));
        ull A2 = add2(P[2], __shfl_xor_sync(0xffffffffu, P[6], 2));
        ull A3 = add2(P[3], __shfl_xor_sync(0xffffffffu, P[7], 2));
        // Round 2 (xor 1): keep quarter q (A0, A1).
        ull F0 = add2(A0, __shfl_xor_sync(0xffffffffu, A2, 1));
        ull F1 = add2(A1, __shfl_xor_sync(0xffffffffu, A3, 1));
        F0 = add2(F0, cA);
        F1 = add2(F1, cB);

        long long p = gtid + (long long)k * stride;
        if (p < total4) {
            float o0, o1, o2, o3;
            unpack2f(F0, o0, o1);
            unpack2f(F1, o2, o3);
            __stcs(&gout[p], make_float4(o0, o1, o2, o3));
        }
    }
}

extern "C" void kernel_launch(void* const* d_in, const int* in_sizes, int n_in,
                              void* d_out, int out_size) {
    // inputs: 0 fp_16 (unused), 1 chem_16, 2 in_proj_weight, 3 in_proj_bias,
    //         4 out_proj_weight, 5 out_proj_bias
    const float* chem  = (const float*)d_in[1];
    const float* w_in  = (const float*)d_in[2];
    const float* b_in  = (const float*)d_in[3];
    const float* w_out = (const float*)d_in[4];
    const float* b_out = (const float*)d_in[5];

    int nrows = in_sizes[1] / DIMN;
    long long total4 = (long long)nrows * 4;

    setup_kernel<<<1, 256>>>(w_in, b_in, w_out, b_out);

    long long blocks = (total4 + 256LL * TPT - 1) / (256LL * TPT);
    long long stride = blocks * 256;   // multiple of 4 -> quarter fixed per thread
    xattn_kernel<<<(int)blocks, 256>>>((const float4*)chem, (float4*)d_out,
                                       total4, stride);
}

// round 7
// speedup vs baseline: 1.6026x; 1.1577x over previous
#include <cuda_runtime.h>

// out = chem @ (Wout @ Wv)^T + (Wout @ bv + bout)   (softmax over singleton == 1)
//
// Partial-sum + butterfly reduce-scatter (R6 scheme), now as a PERSISTENT
// grid with cross-tile software pipelining: ping-pong register buffers so the
// next tile's LDG.128 burst is in flight while the current tile computes and
// stores. Eliminates wave-transition bubbles and sustains MLP continuously.

#define DIMN 16
#define TPT  4            // float4 tasks per thread per tile
#define NCTA 296          // 2 per SM, persistent

typedef unsigned long long ull;

__device__ float2 g_B[128];   // [i*8 + p] = (M[2p][i], M[2p+1][i])
__device__ float2 g_c[8];     // [p]       = (c[2p],    c[2p+1])

__global__ void setup_kernel(const float* __restrict__ w_in,
                             const float* __restrict__ b_in,
                             const float* __restrict__ w_out,
                             const float* __restrict__ b_out) {
    int t = threadIdx.x;
    if (t < 128) {                       // t == i*8 + p
        int i = t >> 3, p = t & 7;
        int j0 = 2 * p, j1 = j0 + 1;
        float m0 = 0.f, m1 = 0.f;
#pragma unroll
        for (int k = 0; k < DIMN; k++) {
            float wv = w_in[(2 * DIMN + k) * DIMN + i];   // Wv rows 32..47, col i
            m0 += w_out[j0 * DIMN + k] * wv;
            m1 += w_out[j1 * DIMN + k] * wv;
        }
        g_B[t] = make_float2(m0, m1);
    }
    if (t < 8) {                         // t == p
        int j0 = 2 * t;
        float c0 = b_out[j0], c1 = b_out[j0 + 1];
#pragma unroll
        for (int k = 0; k < DIMN; k++) {
            float bv = b_in[2 * DIMN + k];
            c0 += w_out[j0 * DIMN + k] * bv;
            c1 += w_out[(j0 + 1) * DIMN + k] * bv;
        }
        g_c[t] = make_float2(c0, c1);
    }
}

__device__ __forceinline__ ull dup2f(float v) {
    ull r;
    asm("mov.b64 %0, {%1, %1};" : "=l"(r) : "f"(v));
    return r;
}
__device__ __forceinline__ void unpack2f(ull v, float& lo, float& hi) {
    asm("mov.b64 {%0, %1}, %2;" : "=f"(lo), "=f"(hi) : "l"(v));
}
__device__ __forceinline__ void ffma2(ull& d, ull a, ull b) {
    asm("fma.rn.f32x2 %0, %1, %2, %3;" : "=l"(d) : "l"(a), "l"(b), "l"(d));
}
__device__ __forceinline__ ull mul2(ull a, ull b) {
    ull r;
    asm("mul.rn.f32x2 %0, %1, %2;" : "=l"(r) : "l"(a), "l"(b));
    return r;
}
__device__ __forceinline__ ull add2(ull a, ull b) {
    ull r;
    asm("add.rn.f32x2 %0, %1, %2;" : "=l"(r) : "l"(a), "l"(b));
    return r;
}

__device__ __forceinline__ void load_tile(float4 v[TPT],
                                          const float4* __restrict__ gin,
                                          long long base, long long total4) {
#pragma unroll
    for (int k = 0; k < TPT; k++) {
        long long p = base + k * 256;
        v[k] = (p < total4) ? __ldcs(&gin[p]) : make_float4(0.f, 0.f, 0.f, 0.f);
    }
}

__device__ __forceinline__ void compute_store(const float4 v[TPT],
                                              float4* __restrict__ gout,
                                              long long base, long long total4,
                                              const ull Mreg[4][8],
                                              ull cA, ull cB) {
#pragma unroll
    for (int k = 0; k < TPT; k++) {
        ull P[8];
        ull xd = dup2f(v[k].x);
#pragma unroll
        for (int m = 0; m < 8; m++) P[m] = mul2(Mreg[0][m], xd);
        xd = dup2f(v[k].y);
#pragma unroll
        for (int m = 0; m < 8; m++) ffma2(P[m], Mreg[1][m], xd);
        xd = dup2f(v[k].z);
#pragma unroll
        for (int m = 0; m < 8; m++) ffma2(P[m], Mreg[2][m], xd);
        xd = dup2f(v[k].w);
#pragma unroll
        for (int m = 0; m < 8; m++) ffma2(P[m], Mreg[3][m], xd);

        // Butterfly reduce-scatter across the lane-quad.
        ull A0 = add2(P[0], __shfl_xor_sync(0xffffffffu, P[4], 2));
        ull A1 = add2(P[1], __shfl_xor_sync(0xffffffffu, P[5], 2));
        ull A2 = add2(P[2], __shfl_xor_sync(0xffffffffu, P[6], 2));
        ull A3 = add2(P[3], __shfl_xor_sync(0xffffffffu, P[7], 2));
        ull F0 = add2(A0, __shfl_xor_sync(0xffffffffu, A2, 1));
        ull F1 = add2(A1, __shfl_xor_sync(0xffffffffu, A3, 1));
        F0 = add2(F0, cA);
        F1 = add2(F1, cB);

        long long p = base + k * 256;
        if (p < total4) {
            float o0, o1, o2, o3;
            unpack2f(F0, o0, o1);
            unpack2f(F1, o2, o3);
            __stcs(&gout[p], make_float4(o0, o1, o2, o3));
        }
    }
}

__global__ __launch_bounds__(256, 2)
void xattn_kernel(const float4* __restrict__ gin,
                  float4* __restrict__ gout,
                  long long total4, int ntiles) {
    __shared__ __align__(16) float2 sB[128];
    __shared__ float2 sC[8];
    int t = threadIdx.x;
    if (t < 128) sB[t] = g_B[t];
    if (t < 8)   sC[t] = g_c[t];
    __syncthreads();

    const int q = t & 3;                 // my input AND output quarter

    // M columns for my input quarter, lane-permuted for constant-index shfl.
    ull Mreg[4][8];
#pragma unroll
    for (int il = 0; il < 4; il++) {
        int i = 4 * q + il;
#pragma unroll
        for (int u = 0; u < 4; u++) {
#pragma unroll
            for (int v = 0; v < 2; v++)
                Mreg[il][2 * u + v] = *(const ull*)&sB[i * 8 + 2 * (q ^ u) + v];
        }
    }
    ull cA = *(const ull*)&sC[2 * q + 0];
    ull cB = *(const ull*)&sC[2 * q + 1];

    const int stride = gridDim.x;
    int tile = blockIdx.x;
    if (tile >= ntiles) return;

    const long long TB = 256LL * TPT;    // float4s per tile
    float4 va[TPT], vb[TPT];

    load_tile(va, gin, (long long)tile * TB + t, total4);

    while (true) {
        int n1 = tile + stride;
        if (n1 < ntiles) load_tile(vb, gin, (long long)n1 * TB + t, total4);
        compute_store(va, gout, (long long)tile * TB + t, total4, Mreg, cA, cB);
        if (n1 >= ntiles) return;

        int n2 = n1 + stride;
        if (n2 < ntiles) load_tile(va, gin, (long long)n2 * TB + t, total4);
        compute_store(vb, gout, (long long)n1 * TB + t, total4, Mreg, cA, cB);
        if (n2 >= ntiles) return;

        tile = n2;
    }
}

extern "C" void kernel_launch(void* const* d_in, const int* in_sizes, int n_in,
                              void* d_out, int out_size) {
    // inputs: 0 fp_16 (unused), 1 chem_16, 2 in_proj_weight, 3 in_proj_bias,
    //         4 out_proj_weight, 5 out_proj_bias
    const float* chem  = (const float*)d_in[1];
    const float* w_in  = (const float*)d_in[2];
    const float* b_in  = (const float*)d_in[3];
    const float* w_out = (const float*)d_in[4];
    const float* b_out = (const float*)d_in[5];

    int nrows = in_sizes[1] / DIMN;
    long long total4 = (long long)nrows * 4;

    setup_kernel<<<1, 256>>>(w_in, b_in, w_out, b_out);

    long long tb = 256LL * TPT;
    int ntiles = (int)((total4 + tb - 1) / tb);
    int blocks = ntiles < NCTA ? ntiles : NCTA;
    xattn_kernel<<<blocks, 256>>>((const float4*)chem, (float4*)d_out,
                                  total4, ntiles);
}